// round 17
// baseline (speedup 1.0000x reference)
#include <cuda_runtime.h>

// Problem shape (fixed by the dataset)
#define BB 256
#define SS 2048
#define HH 128
#define NB 2
#define NTHREADS 512
#define DT 0.1f
#define PAD 36           // floats per 32-float chunk (16B pad kills bank conflicts)
#define HPAD (4 * PAD)   // 144 floats per padded state vector

typedef unsigned long long ull;

// Packed fp32x2 FMA (Blackwell): two fp32 MACs per instruction.
__device__ __forceinline__ ull ffma2(ull a, ull b, ull c) {
    ull d;
    asm("fma.rn.f32x2 %0, %1, %2, %3;" : "=l"(d) : "l"(a), "l"(b), "l"(c));
    return d;
}
__device__ __forceinline__ float fold2(ull a) {
    float lo, hi;
    asm("mov.b64 {%0, %1}, %2;" : "=f"(lo), "=f"(hi) : "l"(a));
    return lo + hi;
}
__device__ __forceinline__ float tanha(float x) {
    float t; asm("tanh.approx.f32 %0, %1;" : "=f"(t) : "f"(x)); return t;
}
__device__ __forceinline__ float shx(float v, int m) {
    return __shfl_xor_sync(0xffffffffu, v, m);
}

// Phase-A reduce (unchanged from the proven R4 kernel): two packed row-partials
// across the 8-lane column group -> full dot for THIS lane's row.
__device__ __forceinline__ float redq2(ull a0, ull a1, bool hiRow) {
    const float s0 = fold2(a0);
    const float s1 = fold2(a1);
    const float x = hiRow ? s0 : s1;
    const float r = shx(x, 4);
    float s = (hiRow ? s1 : s0) + r;
    s += shx(s, 2);
    s += shx(s, 1);
    return s;
}

__global__ void __launch_bounds__(NTHREADS, 1)
liquid_scan_kernel(const float* __restrict__ x,
                   const float* __restrict__ W_in, const float* __restrict__ b_in,
                   const float* __restrict__ W_rec, const float* __restrict__ b_rec,
                   const float* __restrict__ tau,
                   const float* __restrict__ W_att, const float* __restrict__ b_att,
                   const float* __restrict__ W_ev, const float* __restrict__ b_ev,
                   const float* __restrict__ W_acc, const float* __restrict__ b_acc,
                   const float* __restrict__ W_out, const float* __restrict__ b_out,
                   float* __restrict__ out) {
    __shared__ __align__(16) float xs[NB][SS];       // input rows
    __shared__ __align__(16) float ews[NB][SS];      // event weights
    __shared__ __align__(16) float hs[NB][HPAD];     // hidden state (padded chunks)
    __shared__ __align__(16) float hatts[NB][HPAD];  // h * att (padded chunks)

    const int tid = threadIdx.x;
    const int g  = tid >> 3;      // phase-A row-pair group: rows 2g, 2g+1
    const int c  = tid & 7;       // phase-A 16-col block index
    const int h  = tid >> 2;      // row this lane owns (= 2g + bit2 = 4G + (L>>2))
    const int q  = tid & 3;       // lane role
    const int p  = q & 1;         // batch parity for this lane's role
    const bool hiRow = (tid >> 2) & 1;
    const int L  = tid & 15;      // phase-B 16-lane reduce group index
    const int b0 = blockIdx.x * NB;
    const int vbase = 16 * c + 4 * (c >> 1);              // phase-A padded col offset
    const int vb2 = ((L >> 2) * PAD) + 8 * (L & 3);       // phase-B padded col offset (8 cols)
    const int hoff = (h >> 5) * PAD + (h & 31);           // padded scalar index for row h

    // ---- stage x rows into smem
    {
        const float4* xg0 = reinterpret_cast<const float4*>(x + (size_t)b0 * SS);
        const float4* xg1 = reinterpret_cast<const float4*>(x + (size_t)(b0 + 1) * SS);
        reinterpret_cast<float4*>(xs[0])[tid] = xg0[tid];
        reinterpret_cast<float4*>(xs[1])[tid] = xg1[tid];
    }
    if (tid < HPAD) { hs[0][tid] = 0.0f; hs[1][tid] = 0.0f; }
    __syncthreads();

    // ---- precompute event weights into smem AND the event_weights output
    {
        const float wev0 = W_ev[0], wev1 = W_ev[1], bev = b_ev[0];
        float* out_ew = out + BB;
#pragma unroll
        for (int k = 0; k < SS / NTHREADS; k++) {
            const int s = tid + k * NTHREADS;
#pragma unroll
            for (int b = 0; b < NB; b++) {
                float e = 0.0f;
                if (s > 0) {
                    float t = tanha(0.5f * (wev0 * xs[b][s] + wev1 * xs[b][s - 1] + bev));
                    e = fmaf(0.5f, t, 0.5f);
                }
                ews[b][s] = e;
                out_ew[(size_t)(b0 + b) * SS + s] = e;
            }
        }
    }

    // ---- phase-A weights (R4 layout): att + acc, 2 rows x 16 cols each
    ulonglong2 wa[2][4], wc[2][4];
#pragma unroll
    for (int r = 0; r < 2; r++) {
        const int row = 2 * g + r;
        const ulonglong2* Wa = reinterpret_cast<const ulonglong2*>(W_att + row * HH + 16 * c);
        const ulonglong2* Wc = reinterpret_cast<const ulonglong2*>(W_acc + row * HH + 16 * c);
#pragma unroll
        for (int k = 0; k < 4; k++) { wa[r][k] = Wa[k]; wc[r][k] = Wc[k]; }
    }
    // ---- phase-B weights: W_rec as 4 rows x 8 cols, butterfly slot-permuted
    // slot j holds row 4G + ((L>>2) ^ j); cols [8L, 8L+8).
    ulonglong2 wrr[4][2];
#pragma unroll
    for (int j = 0; j < 4; j++) {
        const int row = 4 * (tid >> 4) + (((tid >> 2) & 3) ^ j);
        const ulonglong2* Pr = reinterpret_cast<const ulonglong2*>(W_rec + row * HH + 8 * L);
        wrr[j][0] = Pr[0];
        wrr[j][1] = Pr[1];
    }
    // Lane-role-folded scalars.
    const float pA_bias = (q < 2) ? b_att[h] : b_acc[h];   // phase A bias
    const float brec = b_rec[h];
    const float win  = W_in[h];
    const float bin  = b_in[h];
    const float itau = 1.0f / fminf(fmaxf(tau[h], 0.1f), 10.0f);

    float accq = 0.0f;   // acc state: q2 holds acc[batch0], q3 holds acc[batch1]
    float ewpq = 0.0f;   // previous step's event weight for this lane's batch

    __syncthreads();

#pragma unroll 1
    for (int s = 0; s < SS; s++) {
        // ---- phase A: att + acc matvecs on h_s, batch-sequential (R4, unchanged)
        float A0, C0, A1, C1;
        {
            ull aa0 = 0, aa1 = 0, ac0 = 0, ac1 = 0;
#pragma unroll
            for (int k = 0; k < 4; k++) {
                const ulonglong2 hv = *reinterpret_cast<const ulonglong2*>(&hs[0][vbase + 4 * k]);
                aa0 = ffma2(wa[0][k].x, hv.x, aa0); aa0 = ffma2(wa[0][k].y, hv.y, aa0);
                aa1 = ffma2(wa[1][k].x, hv.x, aa1); aa1 = ffma2(wa[1][k].y, hv.y, aa1);
                ac0 = ffma2(wc[0][k].x, hv.x, ac0); ac0 = ffma2(wc[0][k].y, hv.y, ac0);
                ac1 = ffma2(wc[1][k].x, hv.x, ac1); ac1 = ffma2(wc[1][k].y, hv.y, ac1);
            }
            A0 = redq2(aa0, aa1, hiRow);
            C0 = redq2(ac0, ac1, hiRow);
        }
        {
            ull aa0 = 0, aa1 = 0, ac0 = 0, ac1 = 0;
#pragma unroll
            for (int k = 0; k < 4; k++) {
                const ulonglong2 hv = *reinterpret_cast<const ulonglong2*>(&hs[1][vbase + 4 * k]);
                aa0 = ffma2(wa[0][k].x, hv.x, aa0); aa0 = ffma2(wa[0][k].y, hv.y, aa0);
                aa1 = ffma2(wa[1][k].x, hv.x, aa1); aa1 = ffma2(wa[1][k].y, hv.y, aa1);
                ac0 = ffma2(wc[0][k].x, hv.x, ac0); ac0 = ffma2(wc[0][k].y, hv.y, ac0);
                ac1 = ffma2(wc[1][k].x, hv.x, ac1); ac1 = ffma2(wc[1][k].y, hv.y, ac1);
            }
            A1 = redq2(aa0, aa1, hiRow);
            C1 = redq2(ac0, ac1, hiRow);
        }

        // lane roles: q0->att(b0), q1->att(b1), q2->acc-tanh(b0), q3->acc-tanh(b1)
        const float inA = ((q & 2) ? (p ? C1 : C0) : (p ? A1 : A0)) + pA_bias;
        const float tA = tanha((q < 2) ? 0.5f * inA : inA);
        const float vA = (q < 2) ? fmaf(0.5f, tA, 0.5f) : tA;

        const float hold = hs[p][hoff];          // this lane's batch old h
        if (q < 2) hatts[p][hoff] = hold * vA;   // q0 writes b0, q1 writes b1
        accq = 0.9f * accq + 0.1f * vA * ewpq;   // meaningful on q2/q3 only
        __syncthreads();

        // ---- phase B: rec matvec on h*att, R=4 x C=8 (half the LDS bytes)
        float Rp1, Rp2;
        {
            ull a0 = 0, a1 = 0, a2 = 0, a3 = 0;
            const ulonglong2 v0 = *reinterpret_cast<const ulonglong2*>(&hatts[p][vb2]);
            const ulonglong2 v1 = *reinterpret_cast<const ulonglong2*>(&hatts[p][vb2 + 4]);
            a0 = ffma2(wrr[0][0].x, v0.x, a0); a0 = ffma2(wrr[0][0].y, v0.y, a0);
            a0 = ffma2(wrr[0][1].x, v1.x, a0); a0 = ffma2(wrr[0][1].y, v1.y, a0);
            a1 = ffma2(wrr[1][0].x, v0.x, a1); a1 = ffma2(wrr[1][0].y, v0.y, a1);
            a1 = ffma2(wrr[1][1].x, v1.x, a1); a1 = ffma2(wrr[1][1].y, v1.y, a1);
            a2 = ffma2(wrr[2][0].x, v0.x, a2); a2 = ffma2(wrr[2][0].y, v0.y, a2);
            a2 = ffma2(wrr[2][1].x, v1.x, a2); a2 = ffma2(wrr[2][1].y, v1.y, a2);
            a3 = ffma2(wrr[3][0].x, v0.x, a3); a3 = ffma2(wrr[3][0].y, v0.y, a3);
            a3 = ffma2(wrr[3][1].x, v1.x, a3); a3 = ffma2(wrr[3][1].y, v1.y, a3);
            float f0 = fold2(a0) + shx(fold2(a1), 4);   // xor4: row bit0 (slot-permuted)
            float f2 = fold2(a2) + shx(fold2(a3), 4);
            f0 += shx(f2, 8);                           // xor8: row bit1
            f0 += shx(f0, 2);                           // xor2: role halves all-reduce
            Rp1 = f0;                                   // own batch, own col-half-set
        }
        {
            ull a0 = 0, a1 = 0, a2 = 0, a3 = 0;
            const ulonglong2 v0 = *reinterpret_cast<const ulonglong2*>(&hatts[p ^ 1][vb2]);
            const ulonglong2 v1 = *reinterpret_cast<const ulonglong2*>(&hatts[p ^ 1][vb2 + 4]);
            a0 = ffma2(wrr[0][0].x, v0.x, a0); a0 = ffma2(wrr[0][0].y, v0.y, a0);
            a0 = ffma2(wrr[0][1].x, v1.x, a0); a0 = ffma2(wrr[0][1].y, v1.y, a0);
            a1 = ffma2(wrr[1][0].x, v0.x, a1); a1 = ffma2(wrr[1][0].y, v0.y, a1);
            a1 = ffma2(wrr[1][1].x, v1.x, a1); a1 = ffma2(wrr[1][1].y, v1.y, a1);
            a2 = ffma2(wrr[2][0].x, v0.x, a2); a2 = ffma2(wrr[2][0].y, v0.y, a2);
            a2 = ffma2(wrr[2][1].x, v1.x, a2); a2 = ffma2(wrr[2][1].y, v1.y, a2);
            a3 = ffma2(wrr[3][0].x, v0.x, a3); a3 = ffma2(wrr[3][0].y, v0.y, a3);
            a3 = ffma2(wrr[3][1].x, v1.x, a3); a3 = ffma2(wrr[3][1].y, v1.y, a3);
            float f0 = fold2(a0) + shx(fold2(a1), 4);
            float f2 = fold2(a2) + shx(fold2(a3), 4);
            f0 += shx(f2, 8);
            f0 += shx(f0, 2);
            Rp2 = f0;                                   // other batch, own col-half-set
        }
        // xor1: partner processed batches in opposite order and covers the
        // complementary col-half-set -> full rec dot for (row h, batch p).
        const float R = Rp1 + shx(Rp2, 1);

        const float xq = xs[p][s];
        const float ewq = ews[p][s];
        // lane roles: q0->rec(b0), q1->rec(b1), q2->ic(b0), q3->ic(b1)
        const float inB = (q & 2) ? fmaf(win, xq, bin) : (R + brec);
        const float tB = tanha(inB);
        const float icx = shx(tB, 2);            // q0<-ic0, q1<-ic1
        const float hn = hold + DT * ((icx + tB - hold) * itau) * (1.0f + ewq);
        if (q < 2) hs[p][hoff] = hn;             // q0 writes b0, q1 writes b1
        ewpq = ewq;
        __syncthreads();
    }

    // ---- trailing acc update: tanh(W_acc @ h_S) with ew_{S-1} (phase-A machinery)
    {
        ull c00 = 0, c01 = 0, c10 = 0, c11 = 0;
#pragma unroll
        for (int k = 0; k < 4; k++) {
            const ulonglong2 h0 = *reinterpret_cast<const ulonglong2*>(&hs[0][vbase + 4 * k]);
            const ulonglong2 h1 = *reinterpret_cast<const ulonglong2*>(&hs[1][vbase + 4 * k]);
            c00 = ffma2(wc[0][k].x, h0.x, c00); c00 = ffma2(wc[0][k].y, h0.y, c00);
            c01 = ffma2(wc[1][k].x, h0.x, c01); c01 = ffma2(wc[1][k].y, h0.y, c01);
            c10 = ffma2(wc[0][k].x, h1.x, c10); c10 = ffma2(wc[0][k].y, h1.y, c10);
            c11 = ffma2(wc[1][k].x, h1.x, c11); c11 = ffma2(wc[1][k].y, h1.y, c11);
        }
        const float C0 = redq2(c00, c01, hiRow);
        const float C1 = redq2(c10, c11, hiRow);
        const float t = tanha((p ? C1 : C0) + pA_bias);  // valid on q2/q3 (bias=bacc)
        accq = 0.9f * accq + 0.1f * t * ewpq;
    }

    // ---- epilogue: out[b] = (h_f + acc_f) . W_out + b_out
    if (q & 2) hatts[p][hoff] = accq;   // q2 -> acc[b0], q3 -> acc[b1]
    __syncthreads();
    const int w = tid >> 5, l = tid & 31;
    if (w < NB) {
        float pacc = 0.0f;
#pragma unroll
        for (int i = 0; i < HH / 32; i++) {
            const int jo = i * PAD + l;
            pacc += (hs[w][jo] + hatts[w][jo]) * W_out[l + 32 * i];
        }
#pragma unroll
        for (int o = 16; o; o >>= 1) pacc += shx(pacc, o);
        if (l == 0) out[b0 + w] = pacc + b_out[0];
    }
}

extern "C" void kernel_launch(void* const* d_in, const int* in_sizes, int n_in,
                              void* d_out, int out_size) {
    const float* x     = (const float*)d_in[0];
    const float* W_in  = (const float*)d_in[1];
    const float* b_in  = (const float*)d_in[2];
    const float* W_rec = (const float*)d_in[3];
    const float* b_rec = (const float*)d_in[4];
    const float* tau   = (const float*)d_in[5];
    const float* W_att = (const float*)d_in[6];
    const float* b_att = (const float*)d_in[7];
    const float* W_ev  = (const float*)d_in[8];
    const float* b_ev  = (const float*)d_in[9];
    const float* W_acc = (const float*)d_in[10];
    const float* b_acc = (const float*)d_in[11];
    const float* W_out = (const float*)d_in[12];
    const float* b_out = (const float*)d_in[13];
    float* out = (float*)d_out;

    liquid_scan_kernel<<<BB / NB, NTHREADS>>>(x, W_in, b_in, W_rec, b_rec, tau,
                                              W_att, b_att, W_ev, b_ev,
                                              W_acc, b_acc, W_out, b_out, out);
}